// round 1
// baseline (speedup 1.0000x reference)
#include <cuda_runtime.h>
#include <math.h>

// ---------------------------------------------------------------------------
// Problem constants
// ---------------------------------------------------------------------------
#define BATCH 8
#define CH    512            // C
#define HH    48
#define WW    48
#define HW    2304           // H*W
#define OHW   576            // 24*24 (stride-2 conv output)
#define KIM   4608           // C*3*3 im2col K

// scratch offsets (floats) inside one big __device__ arena
#define OFF_COL    0ull                               // 8*4608*576
#define OFF_QC     21233664ull                        // 8*1024*576
#define OFF_KC     25952256ull                        // 8*512*576
#define OFF_ENERGY 28311552ull                        // 8*1024*512
#define OFF_QP     32505856ull                        // 8*64*2304
#define OFF_KP     33685504ull                        // 8*64*2304
#define OFF_EP     34865152ull                        // 8*2304*2304
#define SCRATCH_TOTAL 77332480ull                     // ~309 MB

__device__ float g_scratch[SCRATCH_TOTAL];

#define OUTC_ELEMS 18874368ull   // 8*1024*2304

// ---------------------------------------------------------------------------
// packed f32x2 helpers (sm_103a: fma.rn.f32x2 runs at 2x FFMA-3reg rate)
// ---------------------------------------------------------------------------
__device__ __forceinline__ void fma2(unsigned long long& d,
                                     unsigned long long a,
                                     unsigned long long b) {
    asm("fma.rn.f32x2 %0, %1, %2, %0;" : "+l"(d) : "l"(a), "l"(b));
}
__device__ __forceinline__ unsigned long long pack2(float x) {
    unsigned long long r;
    asm("mov.b64 %0, {%1, %1};" : "=l"(r) : "f"(x));
    return r;
}

// ---------------------------------------------------------------------------
// Generic tiled SGEMM:  C[M,N] = A[M,K] * B[K,N] (+ bias[m])
//   TA: A stored [K,M] (i.e. we multiply by stored-matrix^T)
//   TB: B stored [N,K]
// 128x128 tile, BK=16, 256 threads, 8x8 per thread, f32x2 packed FMA.
// ---------------------------------------------------------------------------
#define BM 128
#define BN 128
#define BK 16
#define SPAD 4

template <bool TA, bool TB, bool HASBIAS>
__global__ __launch_bounds__(256, 2)
void gemm_kernel(const float* __restrict__ A, int lda, size_t sA,
                 const float* __restrict__ B, int ldb, size_t sB,
                 float* __restrict__ C, int ldc, size_t sC,
                 const float* __restrict__ bias,
                 int M, int N, int K)
{
    __shared__ __align__(16) float As[BK][BM + SPAD];
    __shared__ __align__(16) float Bs[BK][BN + SPAD];

    const int bz = blockIdx.z;
    A += (size_t)bz * sA;
    B += (size_t)bz * sB;
    C += (size_t)bz * sC;

    const int tid  = threadIdx.x;
    const int bm   = blockIdx.y * BM;
    const int bn   = blockIdx.x * BN;
    const int row0 = (tid >> 4) * 8;   // 0..120
    const int col0 = (tid & 15) * 8;   // 0..120

    unsigned long long acc[8][4];
#pragma unroll
    for (int i = 0; i < 8; i++)
#pragma unroll
        for (int j = 0; j < 4; j++) acc[i][j] = 0ull;

    const int tiles = (K + BK - 1) / BK;
    for (int kt = 0; kt < tiles; kt++) {
        const int k0 = kt * BK;

        // ---- load A tile -> As[k][m] ----
#pragma unroll
        for (int i = 0; i < 8; i++) {
            int lin = tid + i * 256;        // 0..2047
            int ml, kl;
            if (!TA) { ml = lin >> 4; kl = lin & 15; }   // storage k-fastest
            else     { kl = lin >> 7; ml = lin & 127; }  // storage m-fastest
            int gm = bm + ml, gk = k0 + kl;
            float v = 0.f;
            if (gm < M && gk < K)
                v = TA ? A[(size_t)gk * lda + gm] : A[(size_t)gm * lda + gk];
            As[kl][ml] = v;
        }
        // ---- load B tile -> Bs[k][n] ----
#pragma unroll
        for (int i = 0; i < 8; i++) {
            int lin = tid + i * 256;
            int nl, kl;
            if (!TB) { kl = lin >> 7; nl = lin & 127; }  // storage n-fastest
            else     { nl = lin >> 4; kl = lin & 15; }   // storage k-fastest
            int gn = bn + nl, gk = k0 + kl;
            float v = 0.f;
            if (gn < N && gk < K)
                v = TB ? B[(size_t)gn * ldb + gk] : B[(size_t)gk * ldb + gn];
            Bs[kl][nl] = v;
        }
        __syncthreads();

#pragma unroll
        for (int k = 0; k < BK; k++) {
            float4 a0 = *reinterpret_cast<const float4*>(&As[k][row0]);
            float4 a1 = *reinterpret_cast<const float4*>(&As[k][row0 + 4]);
            unsigned long long av[8];
            av[0] = pack2(a0.x); av[1] = pack2(a0.y);
            av[2] = pack2(a0.z); av[3] = pack2(a0.w);
            av[4] = pack2(a1.x); av[5] = pack2(a1.y);
            av[6] = pack2(a1.z); av[7] = pack2(a1.w);

            const unsigned long long* bp =
                reinterpret_cast<const unsigned long long*>(&Bs[k][col0]);
            unsigned long long bv[4];
            bv[0] = bp[0]; bv[1] = bp[1]; bv[2] = bp[2]; bv[3] = bp[3];

#pragma unroll
            for (int m = 0; m < 8; m++)
#pragma unroll
                for (int j = 0; j < 4; j++)
                    fma2(acc[m][j], av[m], bv[j]);
        }
        __syncthreads();
    }

    // ---- epilogue ----
#pragma unroll
    for (int m = 0; m < 8; m++) {
        int gm = bm + row0 + m;
        if (gm < M) {
            float bv = HASBIAS ? bias[gm] : 0.f;
            float* crow = C + (size_t)gm * ldc;
#pragma unroll
            for (int j = 0; j < 4; j++) {
                float2 p = *reinterpret_cast<float2*>(&acc[m][j]);
                int gn = bn + col0 + 2 * j;
                if (gn < N)     crow[gn]     = p.x + bv;
                if (gn + 1 < N) crow[gn + 1] = p.y + bv;
            }
        }
    }
}

// ---------------------------------------------------------------------------
// im2col for 3x3 stride-2 pad-1 on 48x48 -> 24x24
// col[b][ic*9+ky*3+kx][oy*24+ox]
// ---------------------------------------------------------------------------
__global__ void im2col_kernel(const float* __restrict__ x, float* __restrict__ col)
{
    size_t i = (size_t)blockIdx.x * blockDim.x + threadIdx.x;  // exact grid
    int pos  = (int)(i % OHW);
    size_t t = i / OHW;
    int kidx = (int)(t % KIM);
    int b    = (int)(t / KIM);

    int ic = kidx / 9;
    int r  = kidx % 9;
    int ky = r / 3, kx = r % 3;
    int oy = pos / 24, ox = pos % 24;
    int iy = oy * 2 - 1 + ky;
    int ix = ox * 2 - 1 + kx;

    float v = 0.f;
    if (iy >= 0 && iy < HH && ix >= 0 && ix < WW)
        v = x[(((size_t)b * CH + ic) * HH + iy) * WW + ix];
    col[i] = v;
}

// ---------------------------------------------------------------------------
// CAM softmax:  attn[q,c] = exp(min_c e - e[q,c]) / sum_c exp(min_c e - e[q,c])
// (equivalent to softmax(max - e) with max-shift; derived analytically)
// one block per row of 512, 256 threads, in-place
// ---------------------------------------------------------------------------
__global__ void softmax_cam(float* __restrict__ e)
{
    float* p = e + (size_t)blockIdx.x * 512;
    int tid = threadIdx.x;
    __shared__ float red[256];

    float v0 = p[tid], v1 = p[tid + 256];
    red[tid] = fminf(v0, v1);
    __syncthreads();
    for (int s = 128; s > 0; s >>= 1) {
        if (tid < s) red[tid] = fminf(red[tid], red[tid + s]);
        __syncthreads();
    }
    float mn = red[0];
    __syncthreads();

    float e0 = expf(mn - v0), e1 = expf(mn - v1);
    red[tid] = e0 + e1;
    __syncthreads();
    for (int s = 128; s > 0; s >>= 1) {
        if (tid < s) red[tid] += red[tid + s];
        __syncthreads();
    }
    float inv = 1.f / red[0];
    p[tid]       = e0 * inv;
    p[tid + 256] = e1 * inv;
}

// ---------------------------------------------------------------------------
// PAM softmax: standard row softmax, row length 2304, 256 threads (9/thread)
// ---------------------------------------------------------------------------
__global__ void softmax_pam(float* __restrict__ e)
{
    float* p = e + (size_t)blockIdx.x * HW;
    int tid = threadIdx.x;
    __shared__ float red[256];

    float v[9];
    float mx = -INFINITY;
#pragma unroll
    for (int i = 0; i < 9; i++) {
        v[i] = p[tid + i * 256];
        mx = fmaxf(mx, v[i]);
    }
    red[tid] = mx;
    __syncthreads();
    for (int s = 128; s > 0; s >>= 1) {
        if (tid < s) red[tid] = fmaxf(red[tid], red[tid + s]);
        __syncthreads();
    }
    mx = red[0];
    __syncthreads();

    float sum = 0.f;
#pragma unroll
    for (int i = 0; i < 9; i++) {
        v[i] = expf(v[i] - mx);
        sum += v[i];
    }
    red[tid] = sum;
    __syncthreads();
    for (int s = 128; s > 0; s >>= 1) {
        if (tid < s) red[tid] += red[tid + s];
        __syncthreads();
    }
    float inv = 1.f / red[0];
#pragma unroll
    for (int i = 0; i < 9; i++) p[tid + i * 256] = v[i] * inv;
}

// ---------------------------------------------------------------------------
// launch
// ---------------------------------------------------------------------------
extern "C" void kernel_launch(void* const* d_in, const int* in_sizes, int n_in,
                              void* d_out, int out_size)
{
    const float* x   = (const float*)d_in[0];
    const float* Wqc = (const float*)d_in[1];
    const float* bqc = (const float*)d_in[2];
    const float* Wkc = (const float*)d_in[3];
    const float* bkc = (const float*)d_in[4];
    const float* Wqp = (const float*)d_in[5];
    const float* bqp = (const float*)d_in[6];
    const float* Wkp = (const float*)d_in[7];
    const float* bkp = (const float*)d_in[8];

    float* outc = (float*)d_out;
    float* outp = outc + OUTC_ELEMS;

    float* scratch = nullptr;
    cudaGetSymbolAddress((void**)&scratch, g_scratch);
    float* col    = scratch + OFF_COL;
    float* qc     = scratch + OFF_QC;
    float* kc     = scratch + OFF_KC;
    float* energy = scratch + OFF_ENERGY;
    float* qp     = scratch + OFF_QP;
    float* kp     = scratch + OFF_KP;
    float* ep     = scratch + OFF_EP;

    // 1. im2col (stride-2 3x3 pad-1)
    im2col_kernel<<<(unsigned)((size_t)BATCH * KIM * OHW / 256), 256>>>(x, col);

    // 2. qc conv: [1024,576] = Wqc[1024,4608] @ col[4608,576]  (+bias)
    gemm_kernel<false, false, true><<<dim3(5, 8, BATCH), 256>>>(
        Wqc, KIM, 0, col, OHW, (size_t)KIM * OHW,
        qc, OHW, (size_t)1024 * OHW, bqc, 1024, OHW, KIM);

    // 3. kc conv: [512,576]
    gemm_kernel<false, false, true><<<dim3(5, 4, BATCH), 256>>>(
        Wkc, KIM, 0, col, OHW, (size_t)KIM * OHW,
        kc, OHW, (size_t)512 * OHW, bkc, 512, OHW, KIM);

    // 4. energy[1024,512] = qc @ kc^T   (NT)
    gemm_kernel<false, true, false><<<dim3(4, 8, BATCH), 256>>>(
        qc, OHW, (size_t)1024 * OHW, kc, OHW, (size_t)512 * OHW,
        energy, 512, (size_t)1024 * 512, nullptr, 1024, 512, OHW);

    // 5. CAM softmax (in-place -> attn_c)
    softmax_cam<<<BATCH * 1024, 256>>>(energy);

    // 6. out_c[1024,2304] = attn_c @ x   (NN)  -> first half of d_out
    gemm_kernel<false, false, false><<<dim3(18, 8, BATCH), 256>>>(
        energy, 512, (size_t)1024 * 512, x, HW, (size_t)CH * HW,
        outc, HW, (size_t)1024 * HW, nullptr, 1024, HW, 512);

    // 7. qp[64,2304] = Wqp[64,512] @ x (+bias);  kp likewise
    gemm_kernel<false, false, true><<<dim3(18, 1, BATCH), 256>>>(
        Wqp, CH, 0, x, HW, (size_t)CH * HW,
        qp, HW, (size_t)64 * HW, bqp, 64, HW, CH);
    gemm_kernel<false, false, true><<<dim3(18, 1, BATCH), 256>>>(
        Wkp, CH, 0, x, HW, (size_t)CH * HW,
        kp, HW, (size_t)64 * HW, bkp, 64, HW, CH);

    // 8. energy_p[2304,2304] = qp^T @ kp   (TN, K=64)
    gemm_kernel<true, false, false><<<dim3(18, 18, BATCH), 256>>>(
        qp, HW, (size_t)64 * HW, kp, HW, (size_t)64 * HW,
        ep, HW, (size_t)HW * HW, nullptr, HW, HW, 64);

    // 9. PAM softmax (in-place -> attn_p)
    softmax_pam<<<BATCH * HW, 256>>>(ep);

    // 10. out_p[1024,2304] = out_c @ attn_p^T   (NT) -> second half of d_out
    gemm_kernel<false, true, false><<<dim3(18, 8, BATCH), 256>>>(
        outc, HW, (size_t)1024 * HW, ep, HW, (size_t)HW * HW,
        outp, HW, (size_t)1024 * HW, nullptr, 1024, HW, HW);
}

// round 2
// speedup vs baseline: 1.8000x; 1.8000x over previous
#include <cuda_runtime.h>
#include <math.h>
#include <stdint.h>

typedef unsigned long long ull;

// ---------------------------------------------------------------------------
// Problem constants
// ---------------------------------------------------------------------------
#define BATCH 8
#define CH    512
#define HH    48
#define WW    48
#define HW    2304
#define OHW   576
#define KIM   4608

#define OFF_COL    0ull
#define OFF_QC     21233664ull
#define OFF_KC     25952256ull
#define OFF_ENERGY 28311552ull
#define OFF_QP     32505856ull
#define OFF_KP     33685504ull
#define OFF_EP     34865152ull
#define SCRATCH_TOTAL 77332480ull

__device__ float g_scratch[SCRATCH_TOTAL];

#define OUTC_ELEMS 18874368ull

// ---------------------------------------------------------------------------
// packed f32x2 helpers
// ---------------------------------------------------------------------------
__device__ __forceinline__ void fma2(ull& d, ull a, ull b) {
    asm("fma.rn.f32x2 %0, %1, %2, %0;" : "+l"(d) : "l"(a), "l"(b));
}
__device__ __forceinline__ ull pack2(float x) {
    ull r;
    asm("mov.b64 %0, {%1, %1};" : "=l"(r) : "f"(x));
    return r;
}
__device__ __forceinline__ uint32_t sptr(const void* p) {
    return (uint32_t)__cvta_generic_to_shared(p);
}

// ---------------------------------------------------------------------------
// SGEMM: C[M,N] = A * B (+bias[m])
//   TA: A stored [K,M] (m-fastest)     else [M,K] (k-fastest)
//   TB: B stored [N,K] (k-fastest)     else [K,N] (n-fastest)
// 128x128 tile, BK=16, 256 thr, 8x8/thread, f32x2, 2-stage pipeline.
// GM_: M may be partial (qp/kp).  GN_: N may be partial (conv, N=576).
// All K are multiples of 16 (no K guards). All partial-N sides are !TB and
// N%4==0 so cp.async src-size zero-fill handles them; TB sides always full-N.
// ---------------------------------------------------------------------------
#define BM 128
#define BN 128
#define BK 16

template <bool TA, bool TB, bool HASBIAS, bool GM_, bool GN_>
__global__ __launch_bounds__(256, 2)
void gemm2(const float* __restrict__ A, int lda, size_t sA,
           const float* __restrict__ B, int ldb, size_t sB,
           float* __restrict__ C, int ldc, size_t sC,
           const float* __restrict__ bias,
           int M, int N, int K)
{
    __shared__ __align__(16) float As[2][BK][BM + 4];
    __shared__ __align__(16) float Bs[2][BK][BN + 4];

    const int bz = blockIdx.z;
    A += (size_t)bz * sA;
    B += (size_t)bz * sB;
    C += (size_t)bz * sC;

    const int tid  = threadIdx.x;
    const int bm   = blockIdx.y * BM;
    const int bn   = blockIdx.x * BN;
    const int row0 = (tid >> 4) * 8;
    const int col0 = (tid & 15) * 8;
    const int T    = K / BK;

    // ---- loaders ----
    auto ldgA = [&](int kt, float4* r) {            // !TA: [M,K] k-fastest
#pragma unroll
        for (int i = 0; i < 2; i++) {
            int lin = tid + i * 256;
            int ml = lin >> 2, kl4 = (lin & 3) * 4;
            int gm = bm + ml;
            if (GM_ && gm >= M) r[i] = make_float4(0.f, 0.f, 0.f, 0.f);
            else r[i] = *(const float4*)(A + (size_t)gm * lda + kt * BK + kl4);
        }
    };
    auto stsA = [&](int s, const float4* r) {
#pragma unroll
        for (int i = 0; i < 2; i++) {
            int lin = tid + i * 256;
            int ml = lin >> 2, kl4 = (lin & 3) * 4;
            As[s][kl4 + 0][ml] = r[i].x;
            As[s][kl4 + 1][ml] = r[i].y;
            As[s][kl4 + 2][ml] = r[i].z;
            As[s][kl4 + 3][ml] = r[i].w;
        }
    };
    auto cpA = [&](int s, int kt) {                 // TA: [K,M] m-fastest
#pragma unroll
        for (int i = 0; i < 2; i++) {
            int lin = tid + i * 256;
            int kl = lin >> 5, ml4 = (lin & 31) * 4;
            uint32_t dst = sptr(&As[s][kl][ml4]);
            const float* src = A + (size_t)(kt * BK + kl) * lda + bm + ml4;
            asm volatile("cp.async.ca.shared.global [%0], [%1], 16;\n"
                         :: "r"(dst), "l"(src));
        }
    };
    auto cpB = [&](int s, int kt) {                 // !TB: [K,N] n-fastest
#pragma unroll
        for (int i = 0; i < 2; i++) {
            int lin = tid + i * 256;
            int kl = lin >> 5, nl4 = (lin & 31) * 4;
            uint32_t dst = sptr(&Bs[s][kl][nl4]);
            if (GN_) {
                int gn = bn + nl4;
                int sz = (gn < N) ? 16 : 0;
                const float* src = B + (size_t)(kt * BK + kl) * ldb + ((gn < N) ? gn : 0);
                asm volatile("cp.async.ca.shared.global [%0], [%1], 16, %2;\n"
                             :: "r"(dst), "l"(src), "r"(sz));
            } else {
                const float* src = B + (size_t)(kt * BK + kl) * ldb + bn + nl4;
                asm volatile("cp.async.ca.shared.global [%0], [%1], 16;\n"
                             :: "r"(dst), "l"(src));
            }
        }
    };
    auto ldgB = [&](int kt, float4* r) {            // TB: [N,K] k-fastest (always full N)
#pragma unroll
        for (int i = 0; i < 2; i++) {
            int lin = tid + i * 256;
            int nl = lin >> 2, kl4 = (lin & 3) * 4;
            r[i] = *(const float4*)(B + (size_t)(bn + nl) * ldb + kt * BK + kl4);
        }
    };
    auto stsB = [&](int s, const float4* r) {
#pragma unroll
        for (int i = 0; i < 2; i++) {
            int lin = tid + i * 256;
            int nl = lin >> 2, kl4 = (lin & 3) * 4;
            Bs[s][kl4 + 0][nl] = r[i].x;
            Bs[s][kl4 + 1][nl] = r[i].y;
            Bs[s][kl4 + 2][nl] = r[i].z;
            Bs[s][kl4 + 3][nl] = r[i].w;
        }
    };

    ull acc[8][4];
#pragma unroll
    for (int i = 0; i < 8; i++)
#pragma unroll
        for (int j = 0; j < 4; j++) acc[i][j] = 0ull;

    // ---- prologue: stage 0 ----
    {
        float4 ra[2], rb[2];
        if (!TA) ldgA(0, ra);
        if (TB)  ldgB(0, rb);
        if (TA)  cpA(0, 0);
        if (!TB) cpB(0, 0);
        if (TA || !TB) asm volatile("cp.async.commit_group;\n");
        if (!TA) stsA(0, ra);
        if (TB)  stsB(0, rb);
        if (TA || !TB) asm volatile("cp.async.wait_group 0;\n");
        __syncthreads();
    }

    // ---- mainloop ----
    for (int kt = 0; kt < T; kt++) {
        const int cur = kt & 1, nxt = cur ^ 1;
        const bool more = (kt + 1) < T;
        float4 ra[2], rb[2];
        if (more) {
            if (!TA) ldgA(kt + 1, ra);          // LDG issued early (async)
            if (TB)  ldgB(kt + 1, rb);
            if (TA)  cpA(nxt, kt + 1);
            if (!TB) cpB(nxt, kt + 1);
            if (TA || !TB) asm volatile("cp.async.commit_group;\n");
        }

#pragma unroll
        for (int k = 0; k < BK; k++) {
            float4 a0 = *(const float4*)&As[cur][k][row0];
            float4 a1 = *(const float4*)&As[cur][k][row0 + 4];
            ull av[8];
            av[0] = pack2(a0.x); av[1] = pack2(a0.y);
            av[2] = pack2(a0.z); av[3] = pack2(a0.w);
            av[4] = pack2(a1.x); av[5] = pack2(a1.y);
            av[6] = pack2(a1.z); av[7] = pack2(a1.w);

            const ull* bp = (const ull*)&Bs[cur][k][col0];
            ull bv[4];
            bv[0] = bp[0]; bv[1] = bp[1]; bv[2] = bp[2]; bv[3] = bp[3];

#pragma unroll
            for (int m = 0; m < 8; m++)
#pragma unroll
                for (int j = 0; j < 4; j++)
                    fma2(acc[m][j], av[m], bv[j]);
        }

        if (more) {
            if (!TA) stsA(nxt, ra);             // STS after compute hid LDG latency
            if (TB)  stsB(nxt, rb);
            if (TA || !TB) asm volatile("cp.async.wait_group 0;\n");
        }
        __syncthreads();
    }

    // ---- epilogue ----
#pragma unroll
    for (int m = 0; m < 8; m++) {
        int gm = bm + row0 + m;
        if (!GM_ || gm < M) {
            float bv = HASBIAS ? bias[gm] : 0.f;
            float* crow = C + (size_t)gm * ldc;
#pragma unroll
            for (int j = 0; j < 4; j++) {
                float2 p = *(float2*)&acc[m][j];
                int gn = bn + col0 + 2 * j;
                if (!GN_ || gn < N) {
                    *(float2*)&crow[gn] = make_float2(p.x + bv, p.y + bv);
                }
            }
        }
    }
}

// ---------------------------------------------------------------------------
// im2col for 3x3 stride-2 pad-1 on 48x48 -> 24x24
// ---------------------------------------------------------------------------
__global__ void im2col_kernel(const float* __restrict__ x, float* __restrict__ col)
{
    size_t i = (size_t)blockIdx.x * blockDim.x + threadIdx.x;
    int pos  = (int)(i % OHW);
    size_t t = i / OHW;
    int kidx = (int)(t % KIM);
    int b    = (int)(t / KIM);

    int ic = kidx / 9;
    int r  = kidx % 9;
    int ky = r / 3, kx = r % 3;
    int oy = pos / 24, ox = pos % 24;
    int iy = oy * 2 - 1 + ky;
    int ix = ox * 2 - 1 + kx;

    float v = 0.f;
    if (iy >= 0 && iy < HH && ix >= 0 && ix < WW)
        v = x[(((size_t)b * CH + ic) * HH + iy) * WW + ix];
    col[i] = v;
}

// ---------------------------------------------------------------------------
// CAM softmax: softmax(max - e) == exp(min - e)/sum  (in-place)
// ---------------------------------------------------------------------------
__global__ void softmax_cam(float* __restrict__ e)
{
    float* p = e + (size_t)blockIdx.x * 512;
    int tid = threadIdx.x;
    __shared__ float red[256];

    float v0 = p[tid], v1 = p[tid + 256];
    red[tid] = fminf(v0, v1);
    __syncthreads();
    for (int s = 128; s > 0; s >>= 1) {
        if (tid < s) red[tid] = fminf(red[tid], red[tid + s]);
        __syncthreads();
    }
    float mn = red[0];
    __syncthreads();

    float e0 = expf(mn - v0), e1 = expf(mn - v1);
    red[tid] = e0 + e1;
    __syncthreads();
    for (int s = 128; s > 0; s >>= 1) {
        if (tid < s) red[tid] += red[tid + s];
        __syncthreads();
    }
    float inv = 1.f / red[0];
    p[tid]       = e0 * inv;
    p[tid + 256] = e1 * inv;
}

// ---------------------------------------------------------------------------
// PAM softmax: row softmax, length 2304
// ---------------------------------------------------------------------------
__global__ void softmax_pam(float* __restrict__ e)
{
    float* p = e + (size_t)blockIdx.x * HW;
    int tid = threadIdx.x;
    __shared__ float red[256];

    float v[9];
    float mx = -INFINITY;
#pragma unroll
    for (int i = 0; i < 9; i++) {
        v[i] = p[tid + i * 256];
        mx = fmaxf(mx, v[i]);
    }
    red[tid] = mx;
    __syncthreads();
    for (int s = 128; s > 0; s >>= 1) {
        if (tid < s) red[tid] = fmaxf(red[tid], red[tid + s]);
        __syncthreads();
    }
    mx = red[0];
    __syncthreads();

    float sum = 0.f;
#pragma unroll
    for (int i = 0; i < 9; i++) {
        v[i] = expf(v[i] - mx);
        sum += v[i];
    }
    red[tid] = sum;
    __syncthreads();
    for (int s = 128; s > 0; s >>= 1) {
        if (tid < s) red[tid] += red[tid + s];
        __syncthreads();
    }
    float inv = 1.f / red[0];
#pragma unroll
    for (int i = 0; i < 9; i++) p[tid + i * 256] = v[i] * inv;
}

// ---------------------------------------------------------------------------
// launch
// ---------------------------------------------------------------------------
extern "C" void kernel_launch(void* const* d_in, const int* in_sizes, int n_in,
                              void* d_out, int out_size)
{
    const float* x   = (const float*)d_in[0];
    const float* Wqc = (const float*)d_in[1];
    const float* bqc = (const float*)d_in[2];
    const float* Wkc = (const float*)d_in[3];
    const float* bkc = (const float*)d_in[4];
    const float* Wqp = (const float*)d_in[5];
    const float* bqp = (const float*)d_in[6];
    const float* Wkp = (const float*)d_in[7];
    const float* bkp = (const float*)d_in[8];

    float* outc = (float*)d_out;
    float* outp = outc + OUTC_ELEMS;

    float* scratch = nullptr;
    cudaGetSymbolAddress((void**)&scratch, g_scratch);
    float* col    = scratch + OFF_COL;
    float* qc     = scratch + OFF_QC;
    float* kc     = scratch + OFF_KC;
    float* energy = scratch + OFF_ENERGY;
    float* qp     = scratch + OFF_QP;
    float* kp     = scratch + OFF_KP;
    float* ep     = scratch + OFF_EP;

    // 1. im2col
    im2col_kernel<<<(unsigned)((size_t)BATCH * KIM * OHW / 256), 256>>>(x, col);

    // 2. qc conv: [1024,576] = Wqc[1024,4608] @ col[4608,576] + bias  (N partial)
    gemm2<false, false, true, false, true><<<dim3(5, 8, BATCH), 256>>>(
        Wqc, KIM, 0, col, OHW, (size_t)KIM * OHW,
        qc, OHW, (size_t)1024 * OHW, bqc, 1024, OHW, KIM);

    // 3. kc conv: [512,576]
    gemm2<false, false, true, false, true><<<dim3(5, 4, BATCH), 256>>>(
        Wkc, KIM, 0, col, OHW, (size_t)KIM * OHW,
        kc, OHW, (size_t)512 * OHW, bkc, 512, OHW, KIM);

    // 4. energy[1024,512] = qc @ kc^T  (NT)
    gemm2<false, true, false, false, false><<<dim3(4, 8, BATCH), 256>>>(
        qc, OHW, (size_t)1024 * OHW, kc, OHW, (size_t)512 * OHW,
        energy, 512, (size_t)1024 * 512, nullptr, 1024, 512, OHW);

    // 5. CAM softmax
    softmax_cam<<<BATCH * 1024, 256>>>(energy);

    // 6. out_c[1024,2304] = attn_c @ x  (NN)
    gemm2<false, false, false, false, false><<<dim3(18, 8, BATCH), 256>>>(
        energy, 512, (size_t)1024 * 512, x, HW, (size_t)CH * HW,
        outc, HW, (size_t)1024 * HW, nullptr, 1024, HW, 512);

    // 7. qp/kp 1x1 convs  (M=64 partial)
    gemm2<false, false, true, true, false><<<dim3(18, 1, BATCH), 256>>>(
        Wqp, CH, 0, x, HW, (size_t)CH * HW,
        qp, HW, (size_t)64 * HW, bqp, 64, HW, CH);
    gemm2<false, false, true, true, false><<<dim3(18, 1, BATCH), 256>>>(
        Wkp, CH, 0, x, HW, (size_t)CH * HW,
        kp, HW, (size_t)64 * HW, bkp, 64, HW, CH);

    // 8. energy_p[2304,2304] = qp^T @ kp  (TN, K=64)
    gemm2<true, false, false, false, false><<<dim3(18, 18, BATCH), 256>>>(
        qp, HW, (size_t)64 * HW, kp, HW, (size_t)64 * HW,
        ep, HW, (size_t)HW * HW, nullptr, HW, HW, 64);

    // 9. PAM softmax
    softmax_pam<<<BATCH * HW, 256>>>(ep);

    // 10. out_p[1024,2304] = out_c @ attn_p^T  (NT)
    gemm2<false, true, false, false, false><<<dim3(18, 8, BATCH), 256>>>(
        outc, HW, (size_t)1024 * HW, ep, HW, (size_t)HW * HW,
        outp, HW, (size_t)1024 * HW, nullptr, 1024, HW, HW);
}